// round 2
// baseline (speedup 1.0000x reference)
#include <cuda_runtime.h>

#define Hh   181
#define KP   184          // K padded to multiple of 4
#define NG   (KP / 4)     // 46 groups of 4 k-steps
#define Tt   1024
#define ROWS 8
#define NBLK 128
#define NTHR 384

// Packed recurrent weights: [k][j] -> (w_r[j,k], w_z[j,k], w_n[j,k], 0)
// One coalesced LDG.128 per thread per k.
__device__ float4 g_wq[KP * Hh];   // 533 KB

__global__ void prep_w_kernel(const float* __restrict__ w_hh) {
    int idx = blockIdx.x * blockDim.x + threadIdx.x;
    if (idx >= KP * Hh) return;
    int k = idx / Hh, j = idx % Hh;
    float4 v = make_float4(0.f, 0.f, 0.f, 0.f);
    if (k < Hh) {
        v.x = w_hh[(j)          * Hh + k];
        v.y = w_hh[(Hh + j)     * Hh + k];
        v.z = w_hh[(2 * Hh + j) * Hh + k];
    }
    g_wq[idx] = v;
}

__global__ __launch_bounds__(NTHR, 1) void gru_kernel(
    const float* __restrict__ x,
    const float* __restrict__ w_ih,
    const float* __restrict__ b_ih,
    const float* __restrict__ b_hh,
    const float* __restrict__ w_fc,
    const float* __restrict__ b_fc,
    float* __restrict__ out)
{
    __shared__ __align__(16) float xs[Tt][ROWS];   // 32 KB: this CTA's x rows
    __shared__ __align__(16) float hT[KP][ROWS];   // h transposed: hT[k][row]

    const int tid = threadIdx.x;
    const int blk = blockIdx.x;

    // Stage x[blk*8 .. blk*8+7][0..1023] into smem (coalesced in t).
    for (int i = tid; i < ROWS * Tt; i += NTHR) {
        int r = i / Tt, t = i % Tt;
        xs[t][r] = x[(blk * ROWS + r) * Tt + t];
    }
    // h0 = 0 (including zero pad rows 181..183 so prefetch reads are clean).
    for (int i = tid; i < KP * ROWS; i += NTHR) ((float*)hT)[i] = 0.f;

    // Thread layout: pair (2j, 2j+1) shares gate-triplet j; even -> rows 0..3, odd -> rows 4..7.
    const int  j   = tid >> 1;
    const int  hi  = tid & 1;
    const bool act = (j < Hh);
    const int  jj  = act ? j : 0;       // inactive threads shadow j=0 (converged, no writes)
    const int  rb  = hi * 4;

    float wihR = 0.f, wihZ = 0.f, wihN = 0.f;
    float bR = 0.f, bZ = 0.f, bihN = 0.f, bhhN = 0.f;
    if (act) {
        wihR = w_ih[j]; wihZ = w_ih[Hh + j]; wihN = w_ih[2 * Hh + j];
        bR   = b_ih[j]          + b_hh[j];
        bZ   = b_ih[Hh + j]     + b_hh[Hh + j];
        bihN = b_ih[2 * Hh + j];
        bhhN = b_hh[2 * Hh + j];
    }

    __syncthreads();

    for (int t = 0; t < Tt; ++t) {
        float aR[4] = {0.f,0.f,0.f,0.f};
        float aZ[4] = {0.f,0.f,0.f,0.f};
        float aN[4] = {0.f,0.f,0.f,0.f};

        // Software pipeline: weights prefetched 2 groups (8 k) ahead, h 1 group ahead.
        float4 wA[4], wB[4], hA[4], hB[4];
        #pragma unroll
        for (int s = 0; s < 4; ++s) {
            wA[s] = g_wq[(0 + s) * Hh + jj];
            wB[s] = g_wq[(4 + s) * Hh + jj];
            hA[s] = *(const float4*)&hT[s][rb];
        }

        #pragma unroll 1
        for (int g = 0; g < NG; g += 2) {
            // ---- phase 1: consume group g (A buffers) ----
            {
                const int gw = min(g + 2, NG - 1);
                const int gh = g + 1;                     // <= 45, always valid
                float4 n0 = g_wq[(gw * 4 + 0) * Hh + jj];
                float4 n1 = g_wq[(gw * 4 + 1) * Hh + jj];
                float4 n2 = g_wq[(gw * 4 + 2) * Hh + jj];
                float4 n3 = g_wq[(gw * 4 + 3) * Hh + jj];
                #pragma unroll
                for (int s = 0; s < 4; ++s)
                    hB[s] = *(const float4*)&hT[gh * 4 + s][rb];
                #pragma unroll
                for (int s = 0; s < 4; ++s) {
                    float4 w4 = wA[s], h4 = hA[s];
                    aR[0] += h4.x * w4.x; aR[1] += h4.y * w4.x; aR[2] += h4.z * w4.x; aR[3] += h4.w * w4.x;
                    aZ[0] += h4.x * w4.y; aZ[1] += h4.y * w4.y; aZ[2] += h4.z * w4.y; aZ[3] += h4.w * w4.y;
                    aN[0] += h4.x * w4.z; aN[1] += h4.y * w4.z; aN[2] += h4.z * w4.z; aN[3] += h4.w * w4.z;
                }
                wA[0] = n0; wA[1] = n1; wA[2] = n2; wA[3] = n3;
            }
            // ---- phase 2: consume group g+1 (B buffers) ----
            {
                const int gw = min(g + 3, NG - 1);
                const int gh = min(g + 2, NG - 1);
                float4 n0 = g_wq[(gw * 4 + 0) * Hh + jj];
                float4 n1 = g_wq[(gw * 4 + 1) * Hh + jj];
                float4 n2 = g_wq[(gw * 4 + 2) * Hh + jj];
                float4 n3 = g_wq[(gw * 4 + 3) * Hh + jj];
                #pragma unroll
                for (int s = 0; s < 4; ++s)
                    hA[s] = *(const float4*)&hT[gh * 4 + s][rb];
                #pragma unroll
                for (int s = 0; s < 4; ++s) {
                    float4 w4 = wB[s], h4 = hB[s];
                    aR[0] += h4.x * w4.x; aR[1] += h4.y * w4.x; aR[2] += h4.z * w4.x; aR[3] += h4.w * w4.x;
                    aZ[0] += h4.x * w4.y; aZ[1] += h4.y * w4.y; aZ[2] += h4.z * w4.y; aZ[3] += h4.w * w4.y;
                    aN[0] += h4.x * w4.z; aN[1] += h4.y * w4.z; aN[2] += h4.z * w4.z; aN[3] += h4.w * w4.z;
                }
                wB[0] = n0; wB[1] = n1; wB[2] = n2; wB[3] = n3;
            }
        }
        __syncthreads();   // all GEMM reads of hT complete

        if (act) {
            float4 xv = *(const float4*)&xs[t][rb];
            float4 ho = *(const float4*)&hT[j][rb];
            float xr[4] = {xv.x, xv.y, xv.z, xv.w};
            float hr[4] = {ho.x, ho.y, ho.z, ho.w};
            float hn[4];
            #pragma unroll
            for (int r = 0; r < 4; ++r) {
                float pr = aR[r] + xr[r] * wihR + bR;
                float rg = __fdividef(1.f, 1.f + __expf(-pr));
                float pz = aZ[r] + xr[r] * wihZ + bZ;
                float zg = __fdividef(1.f, 1.f + __expf(-pz));
                float pn = xr[r] * wihN + bihN + rg * (aN[r] + bhhN);
                float e2 = __expf(-2.f * fabsf(pn));
                float th = copysignf(__fdividef(1.f - e2, 1.f + e2), pn);
                hn[r] = (1.f - zg) * th + zg * hr[r];
            }
            *(float4*)&hT[j][rb] = make_float4(hn[0], hn[1], hn[2], hn[3]);
        }
        __syncthreads();   // h_new visible before next step's GEMM
    }

    // FC epilogue: logits[row, c] = h_last[row,:] . w_fc[c,:] + b_fc[c]
    if (tid < ROWS * 10) {
        int r = tid / 10, c = tid % 10;
        float s = b_fc[c];
        #pragma unroll 4
        for (int k = 0; k < Hh; ++k)
            s += hT[k][r] * __ldg(&w_fc[c * Hh + k]);
        out[(blk * ROWS + r) * 10 + c] = s;
    }
}

extern "C" void kernel_launch(void* const* d_in, const int* in_sizes, int n_in,
                              void* d_out, int out_size) {
    const float* x    = (const float*)d_in[0];
    const float* w_ih = (const float*)d_in[1];
    const float* w_hh = (const float*)d_in[2];
    const float* b_ih = (const float*)d_in[3];
    const float* b_hh = (const float*)d_in[4];
    const float* w_fc = (const float*)d_in[5];
    const float* b_fc = (const float*)d_in[6];

    prep_w_kernel<<<(KP * Hh + 255) / 256, 256>>>(w_hh);
    gru_kernel<<<NBLK, NTHR>>>(x, w_ih, b_ih, b_hh, w_fc, b_fc, (float*)d_out);
}

// round 4
// speedup vs baseline: 1.0031x; 1.0031x over previous
#include <cuda_runtime.h>

#define Hh   181
#define KP   184          // K padded to multiple of 4
#define NG   (KP / 4)     // 46 groups of 4 k-steps
#define Tt   1024
#define ROWS 8
#define NBLK 128
#define NTHR 384

// Packed recurrent weights: [k][j] -> (w_r[j,k], w_z[j,k], w_n[j,k], 0)
// One coalesced LDG.128 per thread per k.
__device__ float4 g_wq[KP * Hh];   // 533 KB

__global__ void prep_w_kernel(const float* __restrict__ w_hh) {
    int idx = blockIdx.x * blockDim.x + threadIdx.x;
    if (idx >= KP * Hh) return;
    int k = idx / Hh, j = idx % Hh;
    float4 v = make_float4(0.f, 0.f, 0.f, 0.f);
    if (k < Hh) {
        v.x = w_hh[(j)          * Hh + k];
        v.y = w_hh[(Hh + j)     * Hh + k];
        v.z = w_hh[(2 * Hh + j) * Hh + k];
    }
    g_wq[idx] = v;
}

__global__ __launch_bounds__(NTHR, 1) void gru_kernel(
    const float* __restrict__ x,
    const float* __restrict__ w_ih,
    const float* __restrict__ b_ih,
    const float* __restrict__ b_hh,
    const float* __restrict__ w_fc,
    const float* __restrict__ b_fc,
    float* __restrict__ out)
{
    __shared__ __align__(16) float xs[Tt][ROWS];   // 32 KB: this CTA's x rows
    __shared__ __align__(16) float hT[KP][ROWS];   // h transposed: hT[k][row]

    const int tid = threadIdx.x;
    const int blk = blockIdx.x;

    // Stage x[blk*8 .. blk*8+7][0..1023] into smem (coalesced in t).
    for (int i = tid; i < ROWS * Tt; i += NTHR) {
        int r = i / Tt, t = i % Tt;
        xs[t][r] = x[(blk * ROWS + r) * Tt + t];
    }
    // h0 = 0 (including zero pad rows 181..183 so prefetch reads are clean).
    for (int i = tid; i < KP * ROWS; i += NTHR) ((float*)hT)[i] = 0.f;

    // Thread layout: pair (2j, 2j+1) shares gate-triplet j; even -> rows 0..3, odd -> rows 4..7.
    const int  j   = tid >> 1;
    const int  hi  = tid & 1;
    const bool act = (j < Hh);
    const int  jj  = act ? j : 0;       // inactive threads shadow j=0 (converged, no writes)
    const int  rb  = hi * 4;

    float wihR = 0.f, wihZ = 0.f, wihN = 0.f;
    float bR = 0.f, bZ = 0.f, bihN = 0.f, bhhN = 0.f;
    if (act) {
        wihR = w_ih[j]; wihZ = w_ih[Hh + j]; wihN = w_ih[2 * Hh + j];
        bR   = b_ih[j]          + b_hh[j];
        bZ   = b_ih[Hh + j]     + b_hh[Hh + j];
        bihN = b_ih[2 * Hh + j];
        bhhN = b_hh[2 * Hh + j];
    }

    __syncthreads();

    for (int t = 0; t < Tt; ++t) {
        float aR[4] = {0.f,0.f,0.f,0.f};
        float aZ[4] = {0.f,0.f,0.f,0.f};
        float aN[4] = {0.f,0.f,0.f,0.f};

        // Software pipeline: weights prefetched 2 groups (8 k) ahead, h 1 group ahead.
        float4 wA[4], wB[4], hA[4], hB[4];
        #pragma unroll
        for (int s = 0; s < 4; ++s) {
            wA[s] = g_wq[(0 + s) * Hh + jj];
            wB[s] = g_wq[(4 + s) * Hh + jj];
            hA[s] = *(const float4*)&hT[s][rb];
        }

        #pragma unroll 1
        for (int g = 0; g < NG; g += 2) {
            // ---- phase 1: consume group g (A buffers) ----
            {
                const int gw = min(g + 2, NG - 1);
                const int gh = g + 1;                     // <= 45, always valid
                float4 n0 = g_wq[(gw * 4 + 0) * Hh + jj];
                float4 n1 = g_wq[(gw * 4 + 1) * Hh + jj];
                float4 n2 = g_wq[(gw * 4 + 2) * Hh + jj];
                float4 n3 = g_wq[(gw * 4 + 3) * Hh + jj];
                #pragma unroll
                for (int s = 0; s < 4; ++s)
                    hB[s] = *(const float4*)&hT[gh * 4 + s][rb];
                #pragma unroll
                for (int s = 0; s < 4; ++s) {
                    float4 w4 = wA[s], h4 = hA[s];
                    aR[0] += h4.x * w4.x; aR[1] += h4.y * w4.x; aR[2] += h4.z * w4.x; aR[3] += h4.w * w4.x;
                    aZ[0] += h4.x * w4.y; aZ[1] += h4.y * w4.y; aZ[2] += h4.z * w4.y; aZ[3] += h4.w * w4.y;
                    aN[0] += h4.x * w4.z; aN[1] += h4.y * w4.z; aN[2] += h4.z * w4.z; aN[3] += h4.w * w4.z;
                }
                wA[0] = n0; wA[1] = n1; wA[2] = n2; wA[3] = n3;
            }
            // ---- phase 2: consume group g+1 (B buffers) ----
            {
                const int gw = min(g + 3, NG - 1);
                const int gh = min(g + 2, NG - 1);
                float4 n0 = g_wq[(gw * 4 + 0) * Hh + jj];
                float4 n1 = g_wq[(gw * 4 + 1) * Hh + jj];
                float4 n2 = g_wq[(gw * 4 + 2) * Hh + jj];
                float4 n3 = g_wq[(gw * 4 + 3) * Hh + jj];
                #pragma unroll
                for (int s = 0; s < 4; ++s)
                    hA[s] = *(const float4*)&hT[gh * 4 + s][rb];
                #pragma unroll
                for (int s = 0; s < 4; ++s) {
                    float4 w4 = wB[s], h4 = hB[s];
                    aR[0] += h4.x * w4.x; aR[1] += h4.y * w4.x; aR[2] += h4.z * w4.x; aR[3] += h4.w * w4.x;
                    aZ[0] += h4.x * w4.y; aZ[1] += h4.y * w4.y; aZ[2] += h4.z * w4.y; aZ[3] += h4.w * w4.y;
                    aN[0] += h4.x * w4.z; aN[1] += h4.y * w4.z; aN[2] += h4.z * w4.z; aN[3] += h4.w * w4.z;
                }
                wB[0] = n0; wB[1] = n1; wB[2] = n2; wB[3] = n3;
            }
        }
        __syncthreads();   // all GEMM reads of hT complete

        if (act) {
            float4 xv = *(const float4*)&xs[t][rb];
            float4 ho = *(const float4*)&hT[j][rb];
            float xr[4] = {xv.x, xv.y, xv.z, xv.w};
            float hr[4] = {ho.x, ho.y, ho.z, ho.w};
            float hn[4];
            #pragma unroll
            for (int r = 0; r < 4; ++r) {
                float pr = aR[r] + xr[r] * wihR + bR;
                float rg = __fdividef(1.f, 1.f + __expf(-pr));
                float pz = aZ[r] + xr[r] * wihZ + bZ;
                float zg = __fdividef(1.f, 1.f + __expf(-pz));
                float pn = xr[r] * wihN + bihN + rg * (aN[r] + bhhN);
                float e2 = __expf(-2.f * fabsf(pn));
                float th = copysignf(__fdividef(1.f - e2, 1.f + e2), pn);
                hn[r] = (1.f - zg) * th + zg * hr[r];
            }
            *(float4*)&hT[j][rb] = make_float4(hn[0], hn[1], hn[2], hn[3]);
        }
        __syncthreads();   // h_new visible before next step's GEMM
    }

    // FC epilogue: logits[row, c] = h_last[row,:] . w_fc[c,:] + b_fc[c]
    if (tid < ROWS * 10) {
        int r = tid / 10, c = tid % 10;
        float s = b_fc[c];
        #pragma unroll 4
        for (int k = 0; k < Hh; ++k)
            s += hT[k][r] * __ldg(&w_fc[c * Hh + k]);
        out[(blk * ROWS + r) * 10 + c] = s;
    }
}

extern "C" void kernel_launch(void* const* d_in, const int* in_sizes, int n_in,
                              void* d_out, int out_size) {
    const float* x    = (const float*)d_in[0];
    const float* w_ih = (const float*)d_in[1];
    const float* w_hh = (const float*)d_in[2];
    const float* b_ih = (const float*)d_in[3];
    const float* b_hh = (const float*)d_in[4];
    const float* w_fc = (const float*)d_in[5];
    const float* b_fc = (const float*)d_in[6];

    prep_w_kernel<<<(KP * Hh + 255) / 256, 256>>>(w_hh);
    gru_kernel<<<NBLK, NTHR>>>(x, w_ih, b_ih, b_hh, w_fc, b_fc, (float*)d_out);
}

// round 8
// speedup vs baseline: 1.2014x; 1.1977x over previous
#include <cuda_runtime.h>
#include <cstdint>

#define Hh   181
#define KK   92           // k-pairs: covers k=0..183 (zeros beyond 180)
#define Tt   1024
#define ROWS 8
#define NBLK 128
#define NTHR 384

// Packed pair weights: [kk*Hh + j]
//   g_wA = (wr[2kk], wr[2kk+1], wz[2kk], wz[2kk+1])
//   g_wN = (wn[2kk], wn[2kk+1])
__device__ __align__(16) float4 g_wA[KK * Hh];   // 266 KB
__device__ __align__(16) float2 g_wN[KK * Hh];   // 133 KB

// packed f32x2 FMA: acc = a*b + acc (two independent fp32 lanes)
#define FMA2(acc, a, b) \
    asm("fma.rn.f32x2 %0, %1, %2, %0;" : "+l"(acc) : "l"(a), "l"(b))

__device__ __forceinline__ float hsum2(unsigned long long v) {
    float lo = __uint_as_float((unsigned)(v & 0xFFFFFFFFull));
    float hi = __uint_as_float((unsigned)(v >> 32));
    return lo + hi;
}

__global__ void prep_w_kernel(const float* __restrict__ w_hh) {
    int idx = blockIdx.x * blockDim.x + threadIdx.x;
    if (idx >= KK * Hh) return;
    int kk = idx / Hh, j = idx % Hh;
    int k0 = 2 * kk, k1 = 2 * kk + 1;
    float r0 = w_hh[j * Hh + k0];                       // k0 <= 182, row j valid
    float r1 = (k1 < Hh) ? w_hh[j * Hh + k1] : 0.f;
    float z0 = w_hh[(Hh + j) * Hh + k0];
    float z1 = (k1 < Hh) ? w_hh[(Hh + j) * Hh + k1] : 0.f;
    float n0 = w_hh[(2 * Hh + j) * Hh + k0];
    float n1 = (k1 < Hh) ? w_hh[(2 * Hh + j) * Hh + k1] : 0.f;
    if (k0 >= Hh) { r0 = z0 = n0 = 0.f; }               // kk=90 pair (180,181): k1 zeroed; kk=91: both
    g_wA[idx] = make_float4(r0, r1, z0, z1);
    g_wN[idx] = make_float2(n0, n1);
}

__global__ __launch_bounds__(NTHR, 1) void gru_kernel(
    const float* __restrict__ x,
    const float* __restrict__ w_ih,
    const float* __restrict__ b_ih,
    const float* __restrict__ b_hh,
    const float* __restrict__ w_fc,
    const float* __restrict__ b_fc,
    float* __restrict__ out)
{
    __shared__ __align__(16) float xs[Tt][ROWS];        // 32 KB
    __shared__ __align__(16) float2 hT2[KK][ROWS];      // 5.75 KB: h pairs, [kk][row]

    const int tid = threadIdx.x;
    const int blk = blockIdx.x;

    // Stage x rows (coalesced in t); zero hT2.
    for (int i = tid; i < ROWS * Tt; i += NTHR) {
        int r = i / Tt, t = i % Tt;
        xs[t][r] = x[(blk * ROWS + r) * Tt + t];
    }
    for (int i = tid; i < KK * ROWS * 2; i += NTHR)
        ((float*)hT2)[i] = 0.f;

    // Thread pair (2j, 2j+1) shares gate j; even -> rows 0..3, odd -> rows 4..7.
    const int  j   = tid >> 1;
    const int  hi  = tid & 1;
    const bool act = (j < Hh);
    const int  jj  = act ? j : 0;
    const int  rb  = hi * 4;

    float wihR = 0.f, wihZ = 0.f, wihN = 0.f;
    float bR = 0.f, bZ = 0.f, bihN = 0.f, bhhN = 0.f;
    if (act) {
        wihR = w_ih[j]; wihZ = w_ih[Hh + j]; wihN = w_ih[2 * Hh + j];
        bR   = b_ih[j]          + b_hh[j];
        bZ   = b_ih[Hh + j]     + b_hh[Hh + j];
        bihN = b_ih[2 * Hh + j];
        bhhN = b_hh[2 * Hh + j];
    }
    float hprev[4] = {0.f, 0.f, 0.f, 0.f};

    __syncthreads();

    for (int t = 0; t < Tt; ++t) {
        unsigned long long aR[4] = {0,0,0,0};
        unsigned long long aZ[4] = {0,0,0,0};
        unsigned long long aN[4] = {0,0,0,0};

        // Software pipeline: prefetch next kk's weights while computing current.
        ulonglong2 w1 = *(const ulonglong2*)&g_wA[jj];
        unsigned long long wn2 = *(const unsigned long long*)&g_wN[jj];

        #pragma unroll 4
        for (int kk = 0; kk < KK; ++kk) {
            ulonglong2 w1n; unsigned long long wn2n;
            if (kk + 1 < KK) {
                w1n  = *(const ulonglong2*)&g_wA[(kk + 1) * Hh + jj];
                wn2n = *(const unsigned long long*)&g_wN[(kk + 1) * Hh + jj];
            } else { w1n.x = w1n.y = 0ull; wn2n = 0ull; }
            ulonglong2 hA = *(const ulonglong2*)&hT2[kk][rb];
            ulonglong2 hB = *(const ulonglong2*)&hT2[kk][rb + 2];
            FMA2(aR[0], w1.x, hA.x); FMA2(aR[1], w1.x, hA.y);
            FMA2(aR[2], w1.x, hB.x); FMA2(aR[3], w1.x, hB.y);
            FMA2(aZ[0], w1.y, hA.x); FMA2(aZ[1], w1.y, hA.y);
            FMA2(aZ[2], w1.y, hB.x); FMA2(aZ[3], w1.y, hB.y);
            FMA2(aN[0], wn2,  hA.x); FMA2(aN[1], wn2,  hA.y);
            FMA2(aN[2], wn2,  hB.x); FMA2(aN[3], wn2,  hB.y);
            w1 = w1n; wn2 = wn2n;
        }
        __syncthreads();   // all GEMM reads of hT2 complete

        if (act) {
            float4 xv = *(const float4*)&xs[t][rb];
            float xr[4] = {xv.x, xv.y, xv.z, xv.w};
            float hn[4];
            #pragma unroll
            for (int r = 0; r < 4; ++r) {
                float pr = hsum2(aR[r]) + xr[r] * wihR + bR;
                float rg = __fdividef(1.f, 1.f + __expf(-pr));
                float pz = hsum2(aZ[r]) + xr[r] * wihZ + bZ;
                float zg = __fdividef(1.f, 1.f + __expf(-pz));
                float pn = xr[r] * wihN + bihN + rg * (hsum2(aN[r]) + bhhN);
                float e2 = __expf(-2.f * fabsf(pn));
                float th = copysignf(__fdividef(1.f - e2, 1.f + e2), pn);
                hn[r] = (1.f - zg) * th + zg * hprev[r];
                hprev[r] = hn[r];
            }
            // scatter into pair layout: component (j&1) of hT2[j>>1][row]
            float* hb = (float*)hT2 + (j >> 1) * (ROWS * 2) + (j & 1);
            hb[(rb + 0) * 2] = hn[0];
            hb[(rb + 1) * 2] = hn[1];
            hb[(rb + 2) * 2] = hn[2];
            hb[(rb + 3) * 2] = hn[3];
        }
        __syncthreads();   // h_new visible before next step's GEMM
    }

    // FC epilogue: logits[row, c] = h_last[row,:] . w_fc[c,:] + b_fc[c]
    if (tid < ROWS * 10) {
        int r = tid / 10, c = tid % 10;
        float s = b_fc[c];
        const float* hb = (const float*)hT2;
        #pragma unroll 4
        for (int k = 0; k < Hh; ++k)
            s += hb[(k >> 1) * (ROWS * 2) + r * 2 + (k & 1)] * __ldg(&w_fc[c * Hh + k]);
        out[(blk * ROWS + r) * 10 + c] = s;
    }
}

extern "C" void kernel_launch(void* const* d_in, const int* in_sizes, int n_in,
                              void* d_out, int out_size) {
    const float* x    = (const float*)d_in[0];
    const float* w_ih = (const float*)d_in[1];
    const float* w_hh = (const float*)d_in[2];
    const float* b_ih = (const float*)d_in[3];
    const float* b_hh = (const float*)d_in[4];
    const float* w_fc = (const float*)d_in[5];
    const float* b_fc = (const float*)d_in[6];

    prep_w_kernel<<<(KK * Hh + 255) / 256, 256>>>(w_hh);
    gru_kernel<<<NBLK, NTHR>>>(x, w_ih, b_ih, b_hh, w_fc, b_fc, (float*)d_out);
}